// round 12
// baseline (speedup 1.0000x reference)
#include <cuda_runtime.h>
#include <cuda_fp16.h>
#include <math.h>
#include <stdint.h>

// Problem constants
#define BN   4096
#define TT   8
#define HH   512
#define NG   2048
#define KK   512                  // inner dim of every GEMM

// plane strides (elements)
#define PS_ENC  ((size_t)32768 * 512)
#define PS_INP0 ((size_t)4096 * 512)
#define PS_W    ((size_t)2048 * 512)
#define PS_W1   ((size_t)512 * 512)
#define PS_H    ((size_t)4096 * 512)

// ---------------- device scratch ----------------
__device__ float g_P[(size_t)BN * 8 * NG];      // input-side gates, row b*8+t
__device__ float g_G[(size_t)BN * NG];          // raw h@Whr^T for current step
__device__ float g_W1E[(size_t)BN * TT * HH];
__device__ float g_brb[NG];
__device__ float g_zero[NG];                    // stays zero (module-load init)
__device__ float g_c  [(size_t)BN * HH];
__device__ float g_hw2[(size_t)BN * HH];
__device__ int   g_sel [BN];
__device__ int   g_mask[BN];

// fp16x2 plane arrays: [plane][rows][512], plane 0 = hi, 1 = lo
__device__ __half g_encP [2 * PS_ENC];
__device__ __half g_inpsP[2 * PS_ENC];
__device__ __half g_inp0P[2 * PS_INP0];
__device__ __half g_WrP  [2 * PS_W];
__device__ __half g_WhrP [2 * PS_W];
__device__ __half g_W1P  [2 * PS_W1];
__device__ __half g_W2P  [2 * PS_W1];
__device__ __half g_hPA  [2 * PS_H];
__device__ __half g_hPB  [2 * PS_H];

// ---------------- streams/events: created once at image load, reused every call
static cudaStream_t g_sA, g_sB;
static cudaEvent_t  g_ev[64];
namespace {
struct StreamInit {
    StreamInit() {
        cudaStreamCreateWithFlags(&g_sA, cudaStreamNonBlocking);
        cudaStreamCreateWithFlags(&g_sB, cudaStreamNonBlocking);
        for (int i = 0; i < 64; i++)
            cudaEventCreateWithFlags(&g_ev[i], cudaEventDisableTiming);
    }
};
StreamInit g_si;
}

__device__ __forceinline__ float sigm(float x) { return 1.0f / (1.0f + expf(-x)); }

__device__ __forceinline__ uint32_t smem_to_u32(const void* p) {
    uint32_t a;
    asm("{ .reg .u64 t; cvta.to.shared.u64 t, %1; cvt.u32.u64 %0, t; }" : "=r"(a) : "l"(p));
    return a;
}
__device__ __forceinline__ void cp16(uint32_t dst, const void* src) {
    asm volatile("cp.async.cg.shared.global [%0], [%1], 16;" :: "r"(dst), "l"(src));
}
__device__ __forceinline__ void ldsm4(uint32_t* r, uint32_t addr) {
    asm volatile("ldmatrix.sync.aligned.m8n8.x4.shared.b16 {%0,%1,%2,%3}, [%4];"
                 : "=r"(r[0]), "=r"(r[1]), "=r"(r[2]), "=r"(r[3]) : "r"(addr));
}
__device__ __forceinline__ void mma16816(float* c, const uint32_t* a, uint32_t b0, uint32_t b1) {
    asm volatile("mma.sync.aligned.m16n8k16.row.col.f32.f16.f16.f32 "
                 "{%0,%1,%2,%3},{%4,%5,%6,%7},{%8,%9},{%0,%1,%2,%3};"
                 : "+f"(c[0]), "+f"(c[1]), "+f"(c[2]), "+f"(c[3])
                 : "r"(a[0]), "r"(a[1]), "r"(a[2]), "r"(a[3]), "r"(b0), "r"(b1));
}

// 2-way fp16 split: x = hi + lo, |lo| <= 2^-11 |x|, dropped lo*lo ~ 2^-22
__device__ __forceinline__ void s2(float x, __half& a, __half& b) {
    a = __float2half_rn(x);
    b = __float2half_rn(x - __half2float(a));
}
__device__ __forceinline__ uint32_t pk2(__half a, __half b) {
    __half2 t = __halves2half2(a, b);
    return *(uint32_t*)&t;
}

// ---------------- small kernels ----------------
__global__ void split_k(const float4* __restrict__ src, __half* __restrict__ dst, size_t n) {
    size_t i = (size_t)blockIdx.x * blockDim.x + threadIdx.x;
    if (i >= (n >> 2)) return;
    float4 v = src[i];
    __half h[4], l[4];
    s2(v.x, h[0], l[0]); s2(v.y, h[1], l[1]);
    s2(v.z, h[2], l[2]); s2(v.w, h[3], l[3]);
    uint2 t;
    t.x = pk2(h[0], h[1]); t.y = pk2(h[2], h[3]);
    *(uint2*)(dst + 4 * i) = t;
    t.x = pk2(l[0], l[1]); t.y = pk2(l[2], l[3]);
    *(uint2*)(dst + n + 4 * i) = t;
}

// reorder LSTM weights to gate-quad order (n = 4*j+g) and split to planes
__global__ void prep_k(const float* __restrict__ Wih, const float* __restrict__ Whh,
                       const float* __restrict__ bih, const float* __restrict__ bhh) {
    int idx = blockIdx.x * blockDim.x + threadIdx.x;   // NG*HH
    int n = idx >> 9, k = idx & 511;
    int j = n >> 2, g = n & 3;
    int src = (g * 512 + j) * 512 + k;
    __half h, l;
    s2(Wih[src], h, l);
    g_WrP[idx] = h; g_WrP[idx + PS_W] = l;
    s2(Whh[src], h, l);
    g_WhrP[idx] = h; g_WhrP[idx + PS_W] = l;
    if (k == 0) g_brb[n] = bih[g * 512 + j] + bhh[g * 512 + j];
}

__global__ void conv_k(const float* __restrict__ enc, const float* __restrict__ cw,
                       const float* __restrict__ cb) {
    int idx = blockIdx.x * blockDim.x + threadIdx.x;   // BN*HH
    int b = idx >> 9, hh = idx & 511;
    const float* e = enc + (size_t)b * TT * HH + hh;
    float s = cb[0];
#pragma unroll
    for (int t = 0; t < TT; t++) s += e[t * HH] * cw[t];
    __half h, l;
    s2(s, h, l);
    g_inp0P[idx] = h; g_inp0P[idx + PS_INP0] = l;
}

__global__ void init_k() {   // mask MUST reset every launch for graph replay
    int idx = blockIdx.x * blockDim.x + threadIdx.x;
    if (idx < BN) g_mask[idx] = 0;
}

// per-step LSTM cell (s>=1): gates = G + P[b*8+sel]; update c; write h planes
__global__ void cell_k(const float* __restrict__ G, __half* __restrict__ houtP) {
    int idx = blockIdx.x * blockDim.x + threadIdx.x;   // BN*HH
    int b = idx >> 9, hidx = idx & 511;
    int sel = g_sel[b];
    float4 gv = *(const float4*)(G + (size_t)b * NG + hidx * 4);
    float4 pv = *(const float4*)(g_P + ((size_t)b * 8 + sel) * NG + hidx * 4);
    float gi = gv.x + pv.x, gf = gv.y + pv.y, gg = gv.z + pv.z, go = gv.w + pv.w;
    float co = g_c[idx];
    float cn = sigm(gf) * co + sigm(gi) * tanhf(gg);
    float hv = sigm(go) * tanhf(cn);
    g_c[idx] = cn;
    __half hh, hl;
    s2(hv, hh, hl);
    houtP[idx] = hh;
    houtP[idx + PS_H] = hl;
}

// ---------------- fp16x2 (3-pass) emulated fp32 GEMM via mma.sync ----------------
// C[m,n] = sum_k A[m,k]*W[n,k], K=512. CTA MTx128, k-chunk 64.
// smem: 2 A planes + 2 B planes (hi, lo). Passes: hi*lo, lo*hi, hi*hi.
// EPI==0: Out[dstrow(m)*ldo+n] = C + bias[n], dstrow=(m/grp)*rowmul+m%grp+rowoff
// EPI==2 (MT=128): step-0 LSTM cell: gates = C + bias(brb); c0=0; write g_c + h planes
template <int EPI, int MT>
__global__ void __launch_bounds__(256, (MT == 128 ? 2 : 3))
tgemm_k(const __half* __restrict__ Ap, size_t APS,
        const __half* __restrict__ Wp, size_t WPS,
        const float* __restrict__ bias,
        float* __restrict__ Out, int ldo,
        int grp, int rowmul, int rowoff,
        __half* __restrict__ houtP) {
    constexpr int MF     = MT / 64;
    constexpr int APL    = MT * 128;         // bytes per A plane tile (64 fp16/row)
    constexpr int ABYTES = 2 * APL;
    constexpr int AQ     = 2 * MT * 8;       // A 16B-quads per chunk
    constexpr int ITER   = (AQ + 2048) / 256;

    extern __shared__ char smc[];
    uint32_t smb = smem_to_u32(smc);
    int tid = threadIdx.x, lane = tid & 31, wid = tid >> 5;
    int wm = wid >> 1, wn = wid & 1;
    int m0 = blockIdx.y * MT, n0 = blockIdx.x * 128;

    int la_r = lane & 15, la_c = (lane >> 4) * 16;
    uint32_t rowA = (uint32_t)(la_r * 128);
    uint32_t swA  = (uint32_t)((la_r & 7) << 4);
    int lb_r = (lane & 7) + ((lane >> 4) & 1) * 8;
    int lb_c = ((lane >> 3) & 1) * 16;
    uint32_t rowB = (uint32_t)(lb_r * 128);
    uint32_t swB  = (uint32_t)((lb_r & 7) << 4);

    float c[MF][8][4];
#pragma unroll
    for (int i = 0; i < MF; i++)
#pragma unroll
        for (int j = 0; j < 8; j++)
#pragma unroll
            for (int q = 0; q < 4; q++) c[i][j][q] = 0.0f;

    for (int kc = 0; kc < 8; kc++) {
        int kb = kc * 64;
#pragma unroll
        for (int it = 0; it < ITER; it++) {
            int q = tid + it * 256;
            const __half* src;
            uint32_t dst;
            if (q < AQ) {
                int tile = q / (MT * 8), rem = q % (MT * 8), row = rem >> 3, c16 = rem & 7;
                src = Ap + (size_t)tile * APS + (size_t)(m0 + row) * KK + kb + c16 * 8;
                dst = smb + tile * APL + row * 128 + ((c16 * 16) ^ ((row & 7) << 4));
            } else {
                int qb = q - AQ;
                int tile = qb >> 10, rem = qb & 1023, row = rem >> 3, c16 = rem & 7;
                src = Wp + (size_t)tile * WPS + (size_t)(n0 + row) * KK + kb + c16 * 8;
                dst = smb + ABYTES + tile * 16384 + row * 128 + ((c16 * 16) ^ ((row & 7) << 4));
            }
            cp16(dst, src);
        }
        asm volatile("cp.async.commit_group;");
        asm volatile("cp.async.wait_group 0;" ::: "memory");
        __syncthreads();

#pragma unroll
        for (int s = 0; s < 4; s++) {
            uint32_t a[2][MF][4];
#pragma unroll
            for (int pl = 0; pl < 2; pl++)
#pragma unroll
                for (int mf = 0; mf < MF; mf++)
                    ldsm4(a[pl][mf],
                          smb + pl * APL + (wm * 16 * MF + mf * 16) * 128 + rowA
                              + (((uint32_t)(la_c + s * 32)) ^ swA));
            // pass order per accumulator (small -> large): hi*lo, lo*hi, hi*hi
#pragma unroll
            for (int pbi = 0; pbi < 2; pbi++) {
                int pb = 1 - pbi;                 // B plane: lo first, then hi
                uint32_t b[4][4];
#pragma unroll
                for (int n2 = 0; n2 < 4; n2++)
                    ldsm4(b[n2], smb + ABYTES + pb * 16384
                                 + (wn * 64 + n2 * 16) * 128 + rowB
                                 + (((uint32_t)(lb_c + s * 32)) ^ swB));
                int npa = (pb == 1) ? 1 : 2;      // pb=1: pa=0; pb=0: pa=1 then 0
#pragma unroll
                for (int pi = 0; pi < 2; pi++) {
                    if (pi >= npa) continue;
                    int pa = (pb == 1) ? 0 : (1 - pi);
#pragma unroll
                    for (int n2 = 0; n2 < 4; n2++) {
#pragma unroll
                        for (int mf = 0; mf < MF; mf++) {
                            mma16816(c[mf][n2 * 2],     a[pa][mf], b[n2][0], b[n2][1]);
                            mma16816(c[mf][n2 * 2 + 1], a[pa][mf], b[n2][2], b[n2][3]);
                        }
                    }
                }
            }
        }
        __syncthreads();
    }

    // stage C to smem: stg[MT][132] fp32
    float* stg = (float*)smc;
#pragma unroll
    for (int mf = 0; mf < MF; mf++)
#pragma unroll
        for (int nf = 0; nf < 8; nf++) {
            int r = wm * 16 * MF + mf * 16 + (lane >> 2);
            int cc = wn * 64 + nf * 8 + (lane & 3) * 2;
            *(float2*)&stg[r * 132 + cc] = make_float2(c[mf][nf][0], c[mf][nf][1]);
            *(float2*)&stg[(r + 8) * 132 + cc] = make_float2(c[mf][nf][2], c[mf][nf][3]);
        }
    __syncthreads();

    if (EPI == 0) {
        constexpr int GPR = 256 / MT;
        constexpr int CPG = 128 / GPR;
        int r = tid / GPR, cb = (tid % GPR) * CPG;
        int gr = m0 + r;
        int dr = (gr / grp) * rowmul + (gr % grp) + rowoff;
        float* op = Out + (size_t)dr * ldo + n0 + cb;
        const float* bp = bias + n0 + cb;
        const float* sr = stg + r * 132 + cb;
#pragma unroll
        for (int j = 0; j < CPG; j += 4) {
            float4 v;
            v.x = sr[j] + bp[j];         v.y = sr[j + 1] + bp[j + 1];
            v.z = sr[j + 2] + bp[j + 2]; v.w = sr[j + 3] + bp[j + 3];
            *(float4*)(op + j) = v;
        }
    } else if (MT == 128) {
        // EPI==2: step-0 LSTM cell, c0 = 0
        int hl = tid & 15, rg = tid >> 4;
#pragma unroll
        for (int i = 0; i < 8; i++) {
            int row = rg * 8 + i, b = m0 + row;
#pragma unroll
            for (int half = 0; half < 2; half++) {
                const float* sr = stg + row * 132 + half * 64 + hl * 4;
                const float* bp = bias + n0 + half * 64 + hl * 4;
                float gi = sr[0] + bp[0];
                float gg = sr[2] + bp[2];
                float go = sr[3] + bp[3];
                int hidx = (n0 >> 2) + half * 16 + hl;
                size_t off = (size_t)b * HH + hidx;
                float cn = sigm(gi) * tanhf(gg);       // sigm(f)*c0 = 0
                float hv = sigm(go) * tanhf(cn);
                g_c[off] = cn;
                __half hh, hlv;
                s2(hv, hh, hlv);
                houtP[off] = hh;
                houtP[off + PS_H] = hlv;
            }
        }
    }
}

// ---------------- fused attention step ----------------
__global__ void attn_k(const float* __restrict__ hw2,
                       const float* __restrict__ vw, const float* __restrict__ vb,
                       float* __restrict__ probs, float* __restrict__ ptrs, int step) {
    __shared__ float red[8][16];
    __shared__ float ui[8];
    int b = blockIdx.x, o = threadIdx.x;

    float hv = hw2[(size_t)b * HH + o];
    float tw = vw[o];
    float part[8];
    const float* we = g_W1E + (size_t)b * TT * HH + o;
#pragma unroll
    for (int t = 0; t < TT; t++) part[t] = tw * tanhf(we[t * HH] + hv);
#pragma unroll
    for (int off = 16; off > 0; off >>= 1)
#pragma unroll
        for (int t = 0; t < TT; t++) part[t] += __shfl_down_sync(0xffffffffu, part[t], off);
    if ((o & 31) == 0) {
        int w = o >> 5;
#pragma unroll
        for (int t = 0; t < TT; t++) red[t][w] = part[t];
    }
    __syncthreads();
    if (o < TT) {
        float s = 0.f;
#pragma unroll
        for (int w = 0; w < 16; w++) s += red[o][w];
        s += vb[0];
        ui[o] = s;
        probs[(size_t)b * (TT * TT) + step * TT + o] = s;
    }
    __syncthreads();
    if (o == 0) {
        int m = g_mask[b];
        int best = 0;
        float bv = -3.4e38f;
#pragma unroll
        for (int t = 0; t < TT; t++) {
            bool ok = ((m >> t) & 1) == 0;
            if (ok && ui[t] > bv) { bv = ui[t]; best = t; }
        }
        g_mask[b] = m | (1 << best);
        g_sel[b] = best;
        ptrs[(size_t)b * TT + step] = (float)best;
    }
}

// ---------------- launch ----------------
#define SMEM128 67584    // max(4*128*128 = 65536 mainloop, 128*132*4 = 67584 staging)
#define SMEM64  49152    // max(48KB mainloop, 64*132*4 = 33792 staging)

extern "C" void kernel_launch(void* const* d_in, const int* in_sizes, int n_in,
                              void* d_out, int out_size) {
    const float* inps   = (const float*)d_in[0];
    const float* enc    = (const float*)d_in[1];
    const float* conv_w = (const float*)d_in[2];
    const float* conv_b = (const float*)d_in[3];
    const float* Wih    = (const float*)d_in[4];
    const float* Whh    = (const float*)d_in[5];
    const float* bih    = (const float*)d_in[6];
    const float* bhh    = (const float*)d_in[7];
    const float* W1     = (const float*)d_in[8];
    const float* b1     = (const float*)d_in[9];
    const float* W2     = (const float*)d_in[10];
    const float* b2     = (const float*)d_in[11];
    const float* vw     = (const float*)d_in[12];
    const float* vb     = (const float*)d_in[13];

    float* probs = (float*)d_out;
    float* ptrs  = probs + (size_t)BN * TT * TT;

    void *pP, *pG, *pW1E, *pbrb, *pzero, *phw2;
    void *pencP, *pinpsP, *pinp0P, *pWrP, *pWhrP, *pW1P, *pW2P, *phPA, *phPB;
    cudaGetSymbolAddress(&pP,     g_P);
    cudaGetSymbolAddress(&pG,     g_G);
    cudaGetSymbolAddress(&pW1E,   g_W1E);
    cudaGetSymbolAddress(&pbrb,   g_brb);
    cudaGetSymbolAddress(&pzero,  g_zero);
    cudaGetSymbolAddress(&phw2,   g_hw2);
    cudaGetSymbolAddress(&pencP,  g_encP);
    cudaGetSymbolAddress(&pinpsP, g_inpsP);
    cudaGetSymbolAddress(&pinp0P, g_inp0P);
    cudaGetSymbolAddress(&pWrP,   g_WrP);
    cudaGetSymbolAddress(&pWhrP,  g_WhrP);
    cudaGetSymbolAddress(&pW1P,   g_W1P);
    cudaGetSymbolAddress(&pW2P,   g_W2P);
    cudaGetSymbolAddress(&phPA,   g_hPA);
    cudaGetSymbolAddress(&phPB,   g_hPB);

    cudaFuncSetAttribute(tgemm_k<0, 128>, cudaFuncAttributeMaxDynamicSharedMemorySize, SMEM128);
    cudaFuncSetAttribute(tgemm_k<2, 128>, cudaFuncAttributeMaxDynamicSharedMemorySize, SMEM128);
    cudaFuncSetAttribute(tgemm_k<0, 64>,  cudaFuncAttributeMaxDynamicSharedMemorySize, SMEM64);

    int ei = 0;
    auto rec = [&](cudaStream_t s) -> cudaEvent_t {
        cudaEventRecord(g_ev[ei], s);
        return g_ev[ei++];
    };

    // ---- fork immediately; prologue split across both streams ----
    cudaEvent_t e0 = rec((cudaStream_t)0);
    cudaStreamWaitEvent(g_sA, e0, 0);
    cudaStreamWaitEvent(g_sB, e0, 0);

    // sA: weights reorder+split, inps split, conv (feeds P / P0 / gates)
    prep_k<<<(NG * HH) / 256, 256, 0, g_sA>>>(Wih, Whh, bih, bhh);
    split_k<<<(int)((PS_ENC / 4 + 255) / 256), 256, 0, g_sA>>>((const float4*)inps,
                                                               (__half*)pinpsP, PS_ENC);
    conv_k<<<(BN * HH) / 256, 256, 0, g_sA>>>(enc, conv_w, conv_b);
    init_k<<<BN / 256, 256, 0, g_sA>>>();

    // sB: enc/W1/W2 splits (feeds W1E / hw2), then W1E GEMM
    split_k<<<(int)((PS_ENC / 4 + 255) / 256), 256, 0, g_sB>>>((const float4*)enc,
                                                               (__half*)pencP, PS_ENC);
    split_k<<<(int)((PS_W1 / 4 + 255) / 256), 256, 0, g_sB>>>((const float4*)W1,
                                                              (__half*)pW1P, PS_W1);
    split_k<<<(int)((PS_W1 / 4 + 255) / 256), 256, 0, g_sB>>>((const float4*)W2,
                                                              (__half*)pW2P, PS_W1);
    {
        dim3 g(HH / 128, (BN * TT) / 128);
        tgemm_k<0, 128><<<g, 256, SMEM128, g_sB>>>((const __half*)pencP, PS_ENC,
                                                   (const __half*)pW1P, PS_W1,
                                                   b1, (float*)pW1E, HH, 1, 1, 0, nullptr);
    }

    // ---- sA: P[b*8+t] = inps[b,t] @ Wr^T + brb ----
    {
        dim3 g(NG / 128, (BN * TT) / 128);
        tgemm_k<0, 128><<<g, 256, SMEM128, g_sA>>>((const __half*)pinpsP, PS_ENC,
                                                   (const __half*)pWrP, PS_W,
                                                   (const float*)pbrb, (float*)pP, NG,
                                                   1, 1, 0, nullptr);
    }
    // ---- sA: step-0 gates GEMM (inp0 @ Wr^T) with fused cell epilogue -> h0, c ----
    {
        dim3 g(NG / 128, BN / 128);
        tgemm_k<2, 128><<<g, 256, SMEM128, g_sA>>>((const __half*)pinp0P, PS_INP0,
                                                   (const __half*)pWrP, PS_W,
                                                   (const float*)pbrb, nullptr, 0,
                                                   1, 1, 0, (__half*)phPA);
    }
    cudaEvent_t e_h = rec(g_sA);        // h0 ready

    cudaEvent_t e_attn;
    // ---- step 0 scoring on sB ----
    cudaStreamWaitEvent(g_sB, e_h, 0);
    {
        dim3 g(HH / 128, BN / 64);
        tgemm_k<0, 64><<<g, 256, SMEM64, g_sB>>>((const __half*)phPA, PS_H,
                                                 (const __half*)pW2P, PS_W1,
                                                 b2, (float*)phw2, HH, 1, 1, 0, nullptr);
    }
    attn_k<<<BN, HH, 0, g_sB>>>((const float*)phw2, vw, vb, probs, ptrs, 0);
    e_attn = rec(g_sB);

    // ---- steps 1..7: gates GEMM (MT=64, less wave quantization) on sA
    //      overlaps prior step's hw2+attn on sB ----
    for (int s = 1; s < TT; s++) {
        const __half* hin = (s & 1) ? (const __half*)phPA : (const __half*)phPB;
        __half* hout      = (s & 1) ? (__half*)phPB : (__half*)phPA;
        {   // raw G = h_{s-1} @ Whr^T  (no sel dependency)
            dim3 g(NG / 128, BN / 64);
            tgemm_k<0, 64><<<g, 256, SMEM64, g_sA>>>(hin, PS_H,
                                                     (const __half*)pWhrP, PS_W,
                                                     (const float*)pzero, (float*)pG, NG,
                                                     1, 1, 0, nullptr);
        }
        cudaStreamWaitEvent(g_sA, e_attn, 0);     // sel_{s-1} needed only by cell
        cell_k<<<(BN * HH) / 256, 256, 0, g_sA>>>((const float*)pG, hout);
        cudaEvent_t e_cell = rec(g_sA);

        cudaStreamWaitEvent(g_sB, e_cell, 0);
        {
            dim3 g(HH / 128, BN / 64);
            tgemm_k<0, 64><<<g, 256, SMEM64, g_sB>>>((const __half*)hout, PS_H,
                                                     (const __half*)pW2P, PS_W1,
                                                     b2, (float*)phw2, HH, 1, 1, 0, nullptr);
        }
        attn_k<<<BN, HH, 0, g_sB>>>((const float*)phw2, vw, vb, probs, ptrs, s);
        e_attn = rec(g_sB);
    }

    // ---- join both streams back into the capture-origin stream ----
    cudaEvent_t eA = rec(g_sA);
    cudaStreamWaitEvent((cudaStream_t)0, eA, 0);
    cudaStreamWaitEvent((cudaStream_t)0, e_attn, 0);
}

// round 13
// speedup vs baseline: 1.0305x; 1.0305x over previous
#include <cuda_runtime.h>
#include <cuda_fp16.h>
#include <math.h>
#include <stdint.h>

// Problem constants
#define BN   4096
#define TT   8
#define HH   512
#define NG   2048
#define KK   512                  // inner dim of every GEMM

// plane strides (elements)
#define PS_ENC  ((size_t)32768 * 512)
#define PS_INP0 ((size_t)4096 * 512)
#define PS_W    ((size_t)2048 * 512)
#define PS_W1   ((size_t)512 * 512)
#define PS_H    ((size_t)4096 * 512)

// ---------------- device scratch ----------------
__device__ float g_P[(size_t)BN * 8 * NG];      // input-side gates, row b*8+t
__device__ float g_G[(size_t)BN * NG];          // raw h@Whr^T for current step
__device__ float g_W1E[(size_t)BN * TT * HH];
__device__ float g_brb[NG];
__device__ float g_zero[NG];                    // stays zero (module-load init)
__device__ float g_c  [(size_t)BN * HH];
__device__ float g_hw2[(size_t)BN * HH];
__device__ int   g_sel [BN];
__device__ int   g_mask[BN];

// fp16x2 plane arrays: [plane][rows][512], plane 0 = hi, 1 = lo
__device__ __half g_encP [2 * PS_ENC];
__device__ __half g_inpsP[2 * PS_ENC];
__device__ __half g_inp0P[2 * PS_INP0];
__device__ __half g_WrP  [2 * PS_W];
__device__ __half g_WhrP [2 * PS_W];
__device__ __half g_W1P  [2 * PS_W1];
__device__ __half g_W2P  [2 * PS_W1];
__device__ __half g_hPA  [2 * PS_H];
__device__ __half g_hPB  [2 * PS_H];

// ---------------- streams/events: created once at image load, reused every call
static cudaStream_t g_sA, g_sB;
static cudaEvent_t  g_ev[64];
namespace {
struct StreamInit {
    StreamInit() {
        cudaStreamCreateWithFlags(&g_sA, cudaStreamNonBlocking);
        cudaStreamCreateWithFlags(&g_sB, cudaStreamNonBlocking);
        for (int i = 0; i < 64; i++)
            cudaEventCreateWithFlags(&g_ev[i], cudaEventDisableTiming);
    }
};
StreamInit g_si;
}

__device__ __forceinline__ float sigm(float x) { return 1.0f / (1.0f + expf(-x)); }

__device__ __forceinline__ uint32_t smem_to_u32(const void* p) {
    uint32_t a;
    asm("{ .reg .u64 t; cvta.to.shared.u64 t, %1; cvt.u32.u64 %0, t; }" : "=r"(a) : "l"(p));
    return a;
}
__device__ __forceinline__ void cp16(uint32_t dst, const void* src) {
    asm volatile("cp.async.cg.shared.global [%0], [%1], 16;" :: "r"(dst), "l"(src));
}
__device__ __forceinline__ void ldsm4(uint32_t* r, uint32_t addr) {
    asm volatile("ldmatrix.sync.aligned.m8n8.x4.shared.b16 {%0,%1,%2,%3}, [%4];"
                 : "=r"(r[0]), "=r"(r[1]), "=r"(r[2]), "=r"(r[3]) : "r"(addr));
}
__device__ __forceinline__ void mma16816(float* c, const uint32_t* a, uint32_t b0, uint32_t b1) {
    asm volatile("mma.sync.aligned.m16n8k16.row.col.f32.f16.f16.f32 "
                 "{%0,%1,%2,%3},{%4,%5,%6,%7},{%8,%9},{%0,%1,%2,%3};"
                 : "+f"(c[0]), "+f"(c[1]), "+f"(c[2]), "+f"(c[3])
                 : "r"(a[0]), "r"(a[1]), "r"(a[2]), "r"(a[3]), "r"(b0), "r"(b1));
}

// 2-way fp16 split: x = hi + lo, |lo| <= 2^-11 |x|, dropped lo*lo ~ 2^-22
__device__ __forceinline__ void s2(float x, __half& a, __half& b) {
    a = __float2half_rn(x);
    b = __float2half_rn(x - __half2float(a));
}
__device__ __forceinline__ uint32_t pk2(__half a, __half b) {
    __half2 t = __halves2half2(a, b);
    return *(uint32_t*)&t;
}

// ---------------- small kernels ----------------
__global__ void split_k(const float4* __restrict__ src, __half* __restrict__ dst, size_t n) {
    size_t i = (size_t)blockIdx.x * blockDim.x + threadIdx.x;
    if (i >= (n >> 2)) return;
    float4 v = src[i];
    __half h[4], l[4];
    s2(v.x, h[0], l[0]); s2(v.y, h[1], l[1]);
    s2(v.z, h[2], l[2]); s2(v.w, h[3], l[3]);
    uint2 t;
    t.x = pk2(h[0], h[1]); t.y = pk2(h[2], h[3]);
    *(uint2*)(dst + 4 * i) = t;
    t.x = pk2(l[0], l[1]); t.y = pk2(l[2], l[3]);
    *(uint2*)(dst + n + 4 * i) = t;
}

// reorder LSTM weights to gate-quad order (n = 4*j+g) and split to planes
__global__ void prep_k(const float* __restrict__ Wih, const float* __restrict__ Whh,
                       const float* __restrict__ bih, const float* __restrict__ bhh) {
    int idx = blockIdx.x * blockDim.x + threadIdx.x;   // NG*HH
    int n = idx >> 9, k = idx & 511;
    int j = n >> 2, g = n & 3;
    int src = (g * 512 + j) * 512 + k;
    __half h, l;
    s2(Wih[src], h, l);
    g_WrP[idx] = h; g_WrP[idx + PS_W] = l;
    s2(Whh[src], h, l);
    g_WhrP[idx] = h; g_WhrP[idx + PS_W] = l;
    if (k == 0) g_brb[n] = bih[g * 512 + j] + bhh[g * 512 + j];
}

__global__ void conv_k(const float* __restrict__ enc, const float* __restrict__ cw,
                       const float* __restrict__ cb) {
    int idx = blockIdx.x * blockDim.x + threadIdx.x;   // BN*HH
    int b = idx >> 9, hh = idx & 511;
    const float* e = enc + (size_t)b * TT * HH + hh;
    float s = cb[0];
#pragma unroll
    for (int t = 0; t < TT; t++) s += e[t * HH] * cw[t];
    __half h, l;
    s2(s, h, l);
    g_inp0P[idx] = h; g_inp0P[idx + PS_INP0] = l;
}

__global__ void init_k() {   // mask MUST reset every launch for graph replay
    int idx = blockIdx.x * blockDim.x + threadIdx.x;
    if (idx < BN) g_mask[idx] = 0;
}

// per-step LSTM cell (s>=1): gates = G + P[b*8+sel]; update c; write h planes
__global__ void cell_k(const float* __restrict__ G, __half* __restrict__ houtP) {
    int idx = blockIdx.x * blockDim.x + threadIdx.x;   // BN*HH
    int b = idx >> 9, hidx = idx & 511;
    int sel = g_sel[b];
    float4 gv = *(const float4*)(G + (size_t)b * NG + hidx * 4);
    float4 pv = *(const float4*)(g_P + ((size_t)b * 8 + sel) * NG + hidx * 4);
    float gi = gv.x + pv.x, gf = gv.y + pv.y, gg = gv.z + pv.z, go = gv.w + pv.w;
    float co = g_c[idx];
    float cn = sigm(gf) * co + sigm(gi) * tanhf(gg);
    float hv = sigm(go) * tanhf(cn);
    g_c[idx] = cn;
    __half hh, hl;
    s2(hv, hh, hl);
    houtP[idx] = hh;
    houtP[idx + PS_H] = hl;
}

// ---------------- fp16x2 (3-pass) emulated fp32 GEMM via mma.sync ----------------
// C[m,n] = sum_k A[m,k]*W[n,k], K=512. CTA MTx128, k-chunk 64.
// smem: 2 A planes + 2 B planes (hi, lo). Passes: hi*lo, lo*hi, hi*hi.
// EPI==0: Out[dstrow(m)*ldo+n] = C + bias[n], dstrow=(m/grp)*rowmul+m%grp+rowoff
// EPI==2 (MT=128): step-0 LSTM cell: gates = C + bias(brb); c0=0; write g_c + h planes
template <int EPI, int MT>
__global__ void __launch_bounds__(256, (MT == 128 ? 2 : 3))
tgemm_k(const __half* __restrict__ Ap, size_t APS,
        const __half* __restrict__ Wp, size_t WPS,
        const float* __restrict__ bias,
        float* __restrict__ Out, int ldo,
        int grp, int rowmul, int rowoff,
        __half* __restrict__ houtP) {
    constexpr int MF     = MT / 64;
    constexpr int APL    = MT * 128;         // bytes per A plane tile (64 fp16/row)
    constexpr int ABYTES = 2 * APL;
    constexpr int AQ     = 2 * MT * 8;       // A 16B-quads per chunk
    constexpr int ITER   = (AQ + 2048) / 256;

    extern __shared__ char smc[];
    uint32_t smb = smem_to_u32(smc);
    int tid = threadIdx.x, lane = tid & 31, wid = tid >> 5;
    int wm = wid >> 1, wn = wid & 1;
    int m0 = blockIdx.y * MT, n0 = blockIdx.x * 128;

    int la_r = lane & 15, la_c = (lane >> 4) * 16;
    uint32_t rowA = (uint32_t)(la_r * 128);
    uint32_t swA  = (uint32_t)((la_r & 7) << 4);
    int lb_r = (lane & 7) + ((lane >> 4) & 1) * 8;
    int lb_c = ((lane >> 3) & 1) * 16;
    uint32_t rowB = (uint32_t)(lb_r * 128);
    uint32_t swB  = (uint32_t)((lb_r & 7) << 4);

    float c[MF][8][4];
#pragma unroll
    for (int i = 0; i < MF; i++)
#pragma unroll
        for (int j = 0; j < 8; j++)
#pragma unroll
            for (int q = 0; q < 4; q++) c[i][j][q] = 0.0f;

    for (int kc = 0; kc < 8; kc++) {
        int kb = kc * 64;
#pragma unroll
        for (int it = 0; it < ITER; it++) {
            int q = tid + it * 256;
            const __half* src;
            uint32_t dst;
            if (q < AQ) {
                int tile = q / (MT * 8), rem = q % (MT * 8), row = rem >> 3, c16 = rem & 7;
                src = Ap + (size_t)tile * APS + (size_t)(m0 + row) * KK + kb + c16 * 8;
                dst = smb + tile * APL + row * 128 + ((c16 * 16) ^ ((row & 7) << 4));
            } else {
                int qb = q - AQ;
                int tile = qb >> 10, rem = qb & 1023, row = rem >> 3, c16 = rem & 7;
                src = Wp + (size_t)tile * WPS + (size_t)(n0 + row) * KK + kb + c16 * 8;
                dst = smb + ABYTES + tile * 16384 + row * 128 + ((c16 * 16) ^ ((row & 7) << 4));
            }
            cp16(dst, src);
        }
        asm volatile("cp.async.commit_group;");
        asm volatile("cp.async.wait_group 0;" ::: "memory");
        __syncthreads();

#pragma unroll
        for (int s = 0; s < 4; s++) {
            uint32_t a[2][MF][4];
#pragma unroll
            for (int pl = 0; pl < 2; pl++)
#pragma unroll
                for (int mf = 0; mf < MF; mf++)
                    ldsm4(a[pl][mf],
                          smb + pl * APL + (wm * 16 * MF + mf * 16) * 128 + rowA
                              + (((uint32_t)(la_c + s * 32)) ^ swA));
            // pass order per accumulator (small -> large): hi*lo, lo*hi, hi*hi
#pragma unroll
            for (int pbi = 0; pbi < 2; pbi++) {
                int pb = 1 - pbi;                 // B plane: lo first, then hi
                uint32_t b[4][4];
#pragma unroll
                for (int n2 = 0; n2 < 4; n2++)
                    ldsm4(b[n2], smb + ABYTES + pb * 16384
                                 + (wn * 64 + n2 * 16) * 128 + rowB
                                 + (((uint32_t)(lb_c + s * 32)) ^ swB));
                int npa = (pb == 1) ? 1 : 2;      // pb=1: pa=0; pb=0: pa=1 then 0
#pragma unroll
                for (int pi = 0; pi < 2; pi++) {
                    if (pi >= npa) continue;
                    int pa = (pb == 1) ? 0 : (1 - pi);
#pragma unroll
                    for (int n2 = 0; n2 < 4; n2++) {
#pragma unroll
                        for (int mf = 0; mf < MF; mf++) {
                            mma16816(c[mf][n2 * 2],     a[pa][mf], b[n2][0], b[n2][1]);
                            mma16816(c[mf][n2 * 2 + 1], a[pa][mf], b[n2][2], b[n2][3]);
                        }
                    }
                }
            }
        }
        __syncthreads();
    }

    // stage C to smem: stg[MT][132] fp32
    float* stg = (float*)smc;
#pragma unroll
    for (int mf = 0; mf < MF; mf++)
#pragma unroll
        for (int nf = 0; nf < 8; nf++) {
            int r = wm * 16 * MF + mf * 16 + (lane >> 2);
            int cc = wn * 64 + nf * 8 + (lane & 3) * 2;
            *(float2*)&stg[r * 132 + cc] = make_float2(c[mf][nf][0], c[mf][nf][1]);
            *(float2*)&stg[(r + 8) * 132 + cc] = make_float2(c[mf][nf][2], c[mf][nf][3]);
        }
    __syncthreads();

    if (EPI == 0) {
        constexpr int GPR = 256 / MT;
        constexpr int CPG = 128 / GPR;
        int r = tid / GPR, cb = (tid % GPR) * CPG;
        int gr = m0 + r;
        int dr = (gr / grp) * rowmul + (gr % grp) + rowoff;
        float* op = Out + (size_t)dr * ldo + n0 + cb;
        const float* bp = bias + n0 + cb;
        const float* sr = stg + r * 132 + cb;
#pragma unroll
        for (int j = 0; j < CPG; j += 4) {
            float4 v;
            v.x = sr[j] + bp[j];         v.y = sr[j + 1] + bp[j + 1];
            v.z = sr[j + 2] + bp[j + 2]; v.w = sr[j + 3] + bp[j + 3];
            *(float4*)(op + j) = v;
        }
    } else if (MT == 128) {
        // EPI==2: step-0 LSTM cell, c0 = 0
        int hl = tid & 15, rg = tid >> 4;
#pragma unroll
        for (int i = 0; i < 8; i++) {
            int row = rg * 8 + i, b = m0 + row;
#pragma unroll
            for (int half = 0; half < 2; half++) {
                const float* sr = stg + row * 132 + half * 64 + hl * 4;
                const float* bp = bias + n0 + half * 64 + hl * 4;
                float gi = sr[0] + bp[0];
                float gg = sr[2] + bp[2];
                float go = sr[3] + bp[3];
                int hidx = (n0 >> 2) + half * 16 + hl;
                size_t off = (size_t)b * HH + hidx;
                float cn = sigm(gi) * tanhf(gg);       // sigm(f)*c0 = 0
                float hv = sigm(go) * tanhf(cn);
                g_c[off] = cn;
                __half hh, hlv;
                s2(hv, hh, hlv);
                houtP[off] = hh;
                houtP[off + PS_H] = hlv;
            }
        }
    }
}

// ---------------- fused attention step ----------------
__global__ void attn_k(const float* __restrict__ hw2,
                       const float* __restrict__ vw, const float* __restrict__ vb,
                       float* __restrict__ probs, float* __restrict__ ptrs, int step) {
    __shared__ float red[8][16];
    __shared__ float ui[8];
    int b = blockIdx.x, o = threadIdx.x;

    float hv = hw2[(size_t)b * HH + o];
    float tw = vw[o];
    float part[8];
    const float* we = g_W1E + (size_t)b * TT * HH + o;
#pragma unroll
    for (int t = 0; t < TT; t++) part[t] = tw * tanhf(we[t * HH] + hv);
#pragma unroll
    for (int off = 16; off > 0; off >>= 1)
#pragma unroll
        for (int t = 0; t < TT; t++) part[t] += __shfl_down_sync(0xffffffffu, part[t], off);
    if ((o & 31) == 0) {
        int w = o >> 5;
#pragma unroll
        for (int t = 0; t < TT; t++) red[t][w] = part[t];
    }
    __syncthreads();
    if (o < TT) {
        float s = 0.f;
#pragma unroll
        for (int w = 0; w < 16; w++) s += red[o][w];
        s += vb[0];
        ui[o] = s;
        probs[(size_t)b * (TT * TT) + step * TT + o] = s;
    }
    __syncthreads();
    if (o == 0) {
        int m = g_mask[b];
        int best = 0;
        float bv = -3.4e38f;
#pragma unroll
        for (int t = 0; t < TT; t++) {
            bool ok = ((m >> t) & 1) == 0;
            if (ok && ui[t] > bv) { bv = ui[t]; best = t; }
        }
        g_mask[b] = m | (1 << best);
        g_sel[b] = best;
        ptrs[(size_t)b * TT + step] = (float)best;
    }
}

// ---------------- launch ----------------
#define SMEM128 67584    // max(4*128*128 = 65536 mainloop, 128*132*4 = 67584 staging)
#define SMEM64  49152    // max(48KB mainloop, 64*132*4 = 33792 staging)

extern "C" void kernel_launch(void* const* d_in, const int* in_sizes, int n_in,
                              void* d_out, int out_size) {
    const float* inps   = (const float*)d_in[0];
    const float* enc    = (const float*)d_in[1];
    const float* conv_w = (const float*)d_in[2];
    const float* conv_b = (const float*)d_in[3];
    const float* Wih    = (const float*)d_in[4];
    const float* Whh    = (const float*)d_in[5];
    const float* bih    = (const float*)d_in[6];
    const float* bhh    = (const float*)d_in[7];
    const float* W1     = (const float*)d_in[8];
    const float* b1     = (const float*)d_in[9];
    const float* W2     = (const float*)d_in[10];
    const float* b2     = (const float*)d_in[11];
    const float* vw     = (const float*)d_in[12];
    const float* vb     = (const float*)d_in[13];

    float* probs = (float*)d_out;
    float* ptrs  = probs + (size_t)BN * TT * TT;

    void *pP, *pG, *pW1E, *pbrb, *pzero, *phw2;
    void *pencP, *pinpsP, *pinp0P, *pWrP, *pWhrP, *pW1P, *pW2P, *phPA, *phPB;
    cudaGetSymbolAddress(&pP,     g_P);
    cudaGetSymbolAddress(&pG,     g_G);
    cudaGetSymbolAddress(&pW1E,   g_W1E);
    cudaGetSymbolAddress(&pbrb,   g_brb);
    cudaGetSymbolAddress(&pzero,  g_zero);
    cudaGetSymbolAddress(&phw2,   g_hw2);
    cudaGetSymbolAddress(&pencP,  g_encP);
    cudaGetSymbolAddress(&pinpsP, g_inpsP);
    cudaGetSymbolAddress(&pinp0P, g_inp0P);
    cudaGetSymbolAddress(&pWrP,   g_WrP);
    cudaGetSymbolAddress(&pWhrP,  g_WhrP);
    cudaGetSymbolAddress(&pW1P,   g_W1P);
    cudaGetSymbolAddress(&pW2P,   g_W2P);
    cudaGetSymbolAddress(&phPA,   g_hPA);
    cudaGetSymbolAddress(&phPB,   g_hPB);

    cudaFuncSetAttribute(tgemm_k<0, 128>, cudaFuncAttributeMaxDynamicSharedMemorySize, SMEM128);
    cudaFuncSetAttribute(tgemm_k<2, 128>, cudaFuncAttributeMaxDynamicSharedMemorySize, SMEM128);
    cudaFuncSetAttribute(tgemm_k<0, 64>,  cudaFuncAttributeMaxDynamicSharedMemorySize, SMEM64);

    int ei = 0;
    auto rec = [&](cudaStream_t s) -> cudaEvent_t {
        cudaEventRecord(g_ev[ei], s);
        return g_ev[ei++];
    };

    // ---- fork immediately; prologue split across both streams ----
    cudaEvent_t e0 = rec((cudaStream_t)0);
    cudaStreamWaitEvent(g_sA, e0, 0);
    cudaStreamWaitEvent(g_sB, e0, 0);

    // sA: weights reorder+split, inps split, conv (feeds P / P0 / gates)
    prep_k<<<(NG * HH) / 256, 256, 0, g_sA>>>(Wih, Whh, bih, bhh);
    split_k<<<(int)((PS_ENC / 4 + 255) / 256), 256, 0, g_sA>>>((const float4*)inps,
                                                               (__half*)pinpsP, PS_ENC);
    conv_k<<<(BN * HH) / 256, 256, 0, g_sA>>>(enc, conv_w, conv_b);
    init_k<<<BN / 256, 256, 0, g_sA>>>();

    // sB: enc/W1/W2 splits (feeds W1E / hw2), then W1E GEMM
    split_k<<<(int)((PS_ENC / 4 + 255) / 256), 256, 0, g_sB>>>((const float4*)enc,
                                                               (__half*)pencP, PS_ENC);
    split_k<<<(int)((PS_W1 / 4 + 255) / 256), 256, 0, g_sB>>>((const float4*)W1,
                                                              (__half*)pW1P, PS_W1);
    split_k<<<(int)((PS_W1 / 4 + 255) / 256), 256, 0, g_sB>>>((const float4*)W2,
                                                              (__half*)pW2P, PS_W1);
    {
        dim3 g(HH / 128, (BN * TT) / 128);
        tgemm_k<0, 128><<<g, 256, SMEM128, g_sB>>>((const __half*)pencP, PS_ENC,
                                                   (const __half*)pW1P, PS_W1,
                                                   b1, (float*)pW1E, HH, 1, 1, 0, nullptr);
    }

    // ---- sA: P[b*8+t] = inps[b,t] @ Wr^T + brb ----
    {
        dim3 g(NG / 128, (BN * TT) / 128);
        tgemm_k<0, 128><<<g, 256, SMEM128, g_sA>>>((const __half*)pinpsP, PS_ENC,
                                                   (const __half*)pWrP, PS_W,
                                                   (const float*)pbrb, (float*)pP, NG,
                                                   1, 1, 0, nullptr);
    }
    // ---- sA: step-0 gates GEMM (inp0 @ Wr^T) with fused cell epilogue -> h0, c ----
    {
        dim3 g(NG / 128, BN / 128);
        tgemm_k<2, 128><<<g, 256, SMEM128, g_sA>>>((const __half*)pinp0P, PS_INP0,
                                                   (const __half*)pWrP, PS_W,
                                                   (const float*)pbrb, nullptr, 0,
                                                   1, 1, 0, (__half*)phPA);
    }
    cudaEvent_t e_h = rec(g_sA);        // h0 ready

    cudaEvent_t e_attn;
    // ---- step 0 scoring on sB ----
    cudaStreamWaitEvent(g_sB, e_h, 0);
    {
        dim3 g(HH / 128, BN / 64);
        tgemm_k<0, 64><<<g, 256, SMEM64, g_sB>>>((const __half*)phPA, PS_H,
                                                 (const __half*)pW2P, PS_W1,
                                                 b2, (float*)phw2, HH, 1, 1, 0, nullptr);
    }
    attn_k<<<BN, HH, 0, g_sB>>>((const float*)phw2, vw, vb, probs, ptrs, 0);
    e_attn = rec(g_sB);

    // ---- steps 1..7: gates GEMM (MT=128, 2 CTA/SM) on sA overlaps
    //      prior step's hw2+attn on sB ----
    for (int s = 1; s < TT; s++) {
        const __half* hin = (s & 1) ? (const __half*)phPA : (const __half*)phPB;
        __half* hout      = (s & 1) ? (__half*)phPB : (__half*)phPA;
        {   // raw G = h_{s-1} @ Whr^T  (no sel dependency)
            dim3 g(NG / 128, BN / 128);
            tgemm_k<0, 128><<<g, 256, SMEM128, g_sA>>>(hin, PS_H,
                                                       (const __half*)pWhrP, PS_W,
                                                       (const float*)pzero, (float*)pG, NG,
                                                       1, 1, 0, nullptr);
        }
        cudaStreamWaitEvent(g_sA, e_attn, 0);     // sel_{s-1} needed only by cell
        cell_k<<<(BN * HH) / 256, 256, 0, g_sA>>>((const float*)pG, hout);
        cudaEvent_t e_cell = rec(g_sA);

        cudaStreamWaitEvent(g_sB, e_cell, 0);
        {
            dim3 g(HH / 128, BN / 64);
            tgemm_k<0, 64><<<g, 256, SMEM64, g_sB>>>((const __half*)hout, PS_H,
                                                     (const __half*)pW2P, PS_W1,
                                                     b2, (float*)phw2, HH, 1, 1, 0, nullptr);
        }
        attn_k<<<BN, HH, 0, g_sB>>>((const float*)phw2, vw, vb, probs, ptrs, s);
        e_attn = rec(g_sB);
    }

    // ---- join both streams back into the capture-origin stream ----
    cudaEvent_t eA = rec(g_sA);
    cudaStreamWaitEvent((cudaStream_t)0, eA, 0);
    cudaStreamWaitEvent((cudaStream_t)0, e_attn, 0);
}

// round 14
// speedup vs baseline: 1.0399x; 1.0092x over previous
#include <cuda_runtime.h>
#include <cuda_fp16.h>
#include <math.h>
#include <stdint.h>

// Problem constants
#define BN   4096
#define TT   8
#define HH   512
#define NG   2048
#define KK   512                  // inner dim of every GEMM

// plane strides (elements)
#define PS_ENC  ((size_t)32768 * 512)
#define PS_INP0 ((size_t)4096 * 512)
#define PS_W    ((size_t)2048 * 512)
#define PS_W1   ((size_t)512 * 512)
#define PS_H    ((size_t)4096 * 512)

// ---------------- device scratch ----------------
__device__ float g_P[(size_t)BN * 8 * NG];      // input-side gates, row b*8+t
__device__ float g_G[(size_t)BN * NG];          // raw h@Whr^T for current step
__device__ float g_W1E[(size_t)BN * TT * HH];
__device__ float g_brb[NG];
__device__ float g_zero[NG];                    // stays zero (module-load init)
__device__ float g_c  [(size_t)BN * HH];
__device__ float g_hw2[(size_t)BN * HH];
__device__ int   g_sel [BN];
__device__ int   g_mask[BN];

// fp16x2 plane arrays: [plane][rows][512], plane 0 = hi, 1 = lo
__device__ __half g_encP [2 * PS_ENC];
__device__ __half g_inpsP[2 * PS_ENC];
__device__ __half g_inp0P[2 * PS_INP0];
__device__ __half g_WrP  [2 * PS_W];
__device__ __half g_WhrP [2 * PS_W];
__device__ __half g_W1P  [2 * PS_W1];
__device__ __half g_W2P  [2 * PS_W1];
__device__ __half g_hPA  [2 * PS_H];
__device__ __half g_hPB  [2 * PS_H];

// ---------------- streams/events: created once at image load, reused every call
static cudaStream_t g_sA, g_sB;
static cudaEvent_t  g_ev[64];
namespace {
struct StreamInit {
    StreamInit() {
        cudaStreamCreateWithFlags(&g_sA, cudaStreamNonBlocking);
        cudaStreamCreateWithFlags(&g_sB, cudaStreamNonBlocking);
        for (int i = 0; i < 64; i++)
            cudaEventCreateWithFlags(&g_ev[i], cudaEventDisableTiming);
    }
};
StreamInit g_si;
}

__device__ __forceinline__ float sigm(float x) { return 1.0f / (1.0f + expf(-x)); }

__device__ __forceinline__ uint32_t smem_to_u32(const void* p) {
    uint32_t a;
    asm("{ .reg .u64 t; cvta.to.shared.u64 t, %1; cvt.u32.u64 %0, t; }" : "=r"(a) : "l"(p));
    return a;
}
__device__ __forceinline__ void cp16(uint32_t dst, const void* src) {
    asm volatile("cp.async.cg.shared.global [%0], [%1], 16;" :: "r"(dst), "l"(src));
}
__device__ __forceinline__ void ldsm4(uint32_t* r, uint32_t addr) {
    asm volatile("ldmatrix.sync.aligned.m8n8.x4.shared.b16 {%0,%1,%2,%3}, [%4];"
                 : "=r"(r[0]), "=r"(r[1]), "=r"(r[2]), "=r"(r[3]) : "r"(addr));
}
__device__ __forceinline__ void mma16816(float* c, const uint32_t* a, uint32_t b0, uint32_t b1) {
    asm volatile("mma.sync.aligned.m16n8k16.row.col.f32.f16.f16.f32 "
                 "{%0,%1,%2,%3},{%4,%5,%6,%7},{%8,%9},{%0,%1,%2,%3};"
                 : "+f"(c[0]), "+f"(c[1]), "+f"(c[2]), "+f"(c[3])
                 : "r"(a[0]), "r"(a[1]), "r"(a[2]), "r"(a[3]), "r"(b0), "r"(b1));
}

// 2-way fp16 split: x = hi + lo, |lo| <= 2^-11 |x|, dropped lo*lo ~ 2^-22
__device__ __forceinline__ void s2(float x, __half& a, __half& b) {
    a = __float2half_rn(x);
    b = __float2half_rn(x - __half2float(a));
}
__device__ __forceinline__ uint32_t pk2(__half a, __half b) {
    __half2 t = __halves2half2(a, b);
    return *(uint32_t*)&t;
}

// ---------------- small kernels ----------------
__global__ void split_k(const float4* __restrict__ src, __half* __restrict__ dst, size_t n) {
    size_t i = (size_t)blockIdx.x * blockDim.x + threadIdx.x;
    if (i >= (n >> 2)) return;
    float4 v = src[i];
    __half h[4], l[4];
    s2(v.x, h[0], l[0]); s2(v.y, h[1], l[1]);
    s2(v.z, h[2], l[2]); s2(v.w, h[3], l[3]);
    uint2 t;
    t.x = pk2(h[0], h[1]); t.y = pk2(h[2], h[3]);
    *(uint2*)(dst + 4 * i) = t;
    t.x = pk2(l[0], l[1]); t.y = pk2(l[2], l[3]);
    *(uint2*)(dst + n + 4 * i) = t;
}

// reorder LSTM weights to gate-quad order (n = 4*j+g) and split to planes
__global__ void prep_k(const float* __restrict__ Wih, const float* __restrict__ Whh,
                       const float* __restrict__ bih, const float* __restrict__ bhh) {
    int idx = blockIdx.x * blockDim.x + threadIdx.x;   // NG*HH
    int n = idx >> 9, k = idx & 511;
    int j = n >> 2, g = n & 3;
    int src = (g * 512 + j) * 512 + k;
    __half h, l;
    s2(Wih[src], h, l);
    g_WrP[idx] = h; g_WrP[idx + PS_W] = l;
    s2(Whh[src], h, l);
    g_WhrP[idx] = h; g_WhrP[idx + PS_W] = l;
    if (k == 0) g_brb[n] = bih[g * 512 + j] + bhh[g * 512 + j];
}

__global__ void conv_k(const float* __restrict__ enc, const float* __restrict__ cw,
                       const float* __restrict__ cb) {
    int idx = blockIdx.x * blockDim.x + threadIdx.x;   // BN*HH
    int b = idx >> 9, hh = idx & 511;
    const float* e = enc + (size_t)b * TT * HH + hh;
    float s = cb[0];
#pragma unroll
    for (int t = 0; t < TT; t++) s += e[t * HH] * cw[t];
    __half h, l;
    s2(s, h, l);
    g_inp0P[idx] = h; g_inp0P[idx + PS_INP0] = l;
}

__global__ void init_k() {   // mask MUST reset every launch for graph replay
    int idx = blockIdx.x * blockDim.x + threadIdx.x;
    if (idx < BN) g_mask[idx] = 0;
}

// per-step LSTM cell (s>=1): gates = G + P[b*8+sel]; update c; write h planes
__global__ void cell_k(const float* __restrict__ G, __half* __restrict__ houtP) {
    int idx = blockIdx.x * blockDim.x + threadIdx.x;   // BN*HH
    int b = idx >> 9, hidx = idx & 511;
    int sel = g_sel[b];
    float4 gv = *(const float4*)(G + (size_t)b * NG + hidx * 4);
    float4 pv = *(const float4*)(g_P + ((size_t)b * 8 + sel) * NG + hidx * 4);
    float gi = gv.x + pv.x, gf = gv.y + pv.y, gg = gv.z + pv.z, go = gv.w + pv.w;
    float co = g_c[idx];
    float cn = sigm(gf) * co + sigm(gi) * tanhf(gg);
    float hv = sigm(go) * tanhf(cn);
    g_c[idx] = cn;
    __half hh, hl;
    s2(hv, hh, hl);
    houtP[idx] = hh;
    houtP[idx + PS_H] = hl;
}

// ---------------- fp16x2 (3-pass) emulated fp32 GEMM via mma.sync ----------------
// C[m,n] = sum_k A[m,k]*W[n,k], K=512. CTA MTx128, k-chunk 64.
// smem: 2 A planes + 2 B planes (hi, lo). Passes: hi*lo, lo*hi, hi*hi.
// EPI==0: Out[dstrow(m)*ldo+n] = C + bias[n], dstrow=(m/grp)*rowmul+m%grp+rowoff
// EPI==2 (MT=128): step-0 LSTM cell: gates = C + bias(brb); c0=0; write g_c + h planes
template <int EPI, int MT>
__global__ void __launch_bounds__(256, (MT == 128 ? 2 : 3))
tgemm_k(const __half* __restrict__ Ap, size_t APS,
        const __half* __restrict__ Wp, size_t WPS,
        const float* __restrict__ bias,
        float* __restrict__ Out, int ldo,
        int grp, int rowmul, int rowoff,
        __half* __restrict__ houtP) {
    constexpr int MF     = MT / 64;
    constexpr int APL    = MT * 128;         // bytes per A plane tile (64 fp16/row)
    constexpr int ABYTES = 2 * APL;
    constexpr int AQ     = 2 * MT * 8;       // A 16B-quads per chunk
    constexpr int ITER   = (AQ + 2048) / 256;

    extern __shared__ char smc[];
    uint32_t smb = smem_to_u32(smc);
    int tid = threadIdx.x, lane = tid & 31, wid = tid >> 5;
    int wm = wid >> 1, wn = wid & 1;
    int m0 = blockIdx.y * MT, n0 = blockIdx.x * 128;

    int la_r = lane & 15, la_c = (lane >> 4) * 16;
    uint32_t rowA = (uint32_t)(la_r * 128);
    uint32_t swA  = (uint32_t)((la_r & 7) << 4);
    int lb_r = (lane & 7) + ((lane >> 4) & 1) * 8;
    int lb_c = ((lane >> 3) & 1) * 16;
    uint32_t rowB = (uint32_t)(lb_r * 128);
    uint32_t swB  = (uint32_t)((lb_r & 7) << 4);

    float c[MF][8][4];
#pragma unroll
    for (int i = 0; i < MF; i++)
#pragma unroll
        for (int j = 0; j < 8; j++)
#pragma unroll
            for (int q = 0; q < 4; q++) c[i][j][q] = 0.0f;

    for (int kc = 0; kc < 8; kc++) {
        int kb = kc * 64;
#pragma unroll
        for (int it = 0; it < ITER; it++) {
            int q = tid + it * 256;
            const __half* src;
            uint32_t dst;
            if (q < AQ) {
                int tile = q / (MT * 8), rem = q % (MT * 8), row = rem >> 3, c16 = rem & 7;
                src = Ap + (size_t)tile * APS + (size_t)(m0 + row) * KK + kb + c16 * 8;
                dst = smb + tile * APL + row * 128 + ((c16 * 16) ^ ((row & 7) << 4));
            } else {
                int qb = q - AQ;
                int tile = qb >> 10, rem = qb & 1023, row = rem >> 3, c16 = rem & 7;
                src = Wp + (size_t)tile * WPS + (size_t)(n0 + row) * KK + kb + c16 * 8;
                dst = smb + ABYTES + tile * 16384 + row * 128 + ((c16 * 16) ^ ((row & 7) << 4));
            }
            cp16(dst, src);
        }
        asm volatile("cp.async.commit_group;");
        asm volatile("cp.async.wait_group 0;" ::: "memory");
        __syncthreads();

#pragma unroll
        for (int s = 0; s < 4; s++) {
            uint32_t a[2][MF][4];
#pragma unroll
            for (int pl = 0; pl < 2; pl++)
#pragma unroll
                for (int mf = 0; mf < MF; mf++)
                    ldsm4(a[pl][mf],
                          smb + pl * APL + (wm * 16 * MF + mf * 16) * 128 + rowA
                              + (((uint32_t)(la_c + s * 32)) ^ swA));
            // pass order per accumulator (small -> large): hi*lo, lo*hi, hi*hi
#pragma unroll
            for (int pbi = 0; pbi < 2; pbi++) {
                int pb = 1 - pbi;                 // B plane: lo first, then hi
                uint32_t b[4][4];
#pragma unroll
                for (int n2 = 0; n2 < 4; n2++)
                    ldsm4(b[n2], smb + ABYTES + pb * 16384
                                 + (wn * 64 + n2 * 16) * 128 + rowB
                                 + (((uint32_t)(lb_c + s * 32)) ^ swB));
                int npa = (pb == 1) ? 1 : 2;      // pb=1: pa=0; pb=0: pa=1 then 0
#pragma unroll
                for (int pi = 0; pi < 2; pi++) {
                    if (pi >= npa) continue;
                    int pa = (pb == 1) ? 0 : (1 - pi);
#pragma unroll
                    for (int n2 = 0; n2 < 4; n2++) {
#pragma unroll
                        for (int mf = 0; mf < MF; mf++) {
                            mma16816(c[mf][n2 * 2],     a[pa][mf], b[n2][0], b[n2][1]);
                            mma16816(c[mf][n2 * 2 + 1], a[pa][mf], b[n2][2], b[n2][3]);
                        }
                    }
                }
            }
        }
        __syncthreads();
    }

    // stage C to smem: stg[MT][132] fp32
    float* stg = (float*)smc;
#pragma unroll
    for (int mf = 0; mf < MF; mf++)
#pragma unroll
        for (int nf = 0; nf < 8; nf++) {
            int r = wm * 16 * MF + mf * 16 + (lane >> 2);
            int cc = wn * 64 + nf * 8 + (lane & 3) * 2;
            *(float2*)&stg[r * 132 + cc] = make_float2(c[mf][nf][0], c[mf][nf][1]);
            *(float2*)&stg[(r + 8) * 132 + cc] = make_float2(c[mf][nf][2], c[mf][nf][3]);
        }
    __syncthreads();

    if (EPI == 0) {
        constexpr int GPR = 256 / MT;
        constexpr int CPG = 128 / GPR;
        int r = tid / GPR, cb = (tid % GPR) * CPG;
        int gr = m0 + r;
        int dr = (gr / grp) * rowmul + (gr % grp) + rowoff;
        float* op = Out + (size_t)dr * ldo + n0 + cb;
        const float* bp = bias + n0 + cb;
        const float* sr = stg + r * 132 + cb;
#pragma unroll
        for (int j = 0; j < CPG; j += 4) {
            float4 v;
            v.x = sr[j] + bp[j];         v.y = sr[j + 1] + bp[j + 1];
            v.z = sr[j + 2] + bp[j + 2]; v.w = sr[j + 3] + bp[j + 3];
            *(float4*)(op + j) = v;
        }
    } else if (MT == 128) {
        // EPI==2: step-0 LSTM cell, c0 = 0
        int hl = tid & 15, rg = tid >> 4;
#pragma unroll
        for (int i = 0; i < 8; i++) {
            int row = rg * 8 + i, b = m0 + row;
#pragma unroll
            for (int half = 0; half < 2; half++) {
                const float* sr = stg + row * 132 + half * 64 + hl * 4;
                const float* bp = bias + n0 + half * 64 + hl * 4;
                float gi = sr[0] + bp[0];
                float gg = sr[2] + bp[2];
                float go = sr[3] + bp[3];
                int hidx = (n0 >> 2) + half * 16 + hl;
                size_t off = (size_t)b * HH + hidx;
                float cn = sigm(gi) * tanhf(gg);       // sigm(f)*c0 = 0
                float hv = sigm(go) * tanhf(cn);
                g_c[off] = cn;
                __half hh, hlv;
                s2(hv, hh, hlv);
                houtP[off] = hh;
                houtP[off + PS_H] = hlv;
            }
        }
    }
}

// ---------------- fused attention step ----------------
__global__ void attn_k(const float* __restrict__ hw2,
                       const float* __restrict__ vw, const float* __restrict__ vb,
                       float* __restrict__ probs, float* __restrict__ ptrs, int step) {
    __shared__ float red[8][16];
    __shared__ float ui[8];
    int b = blockIdx.x, o = threadIdx.x;

    float hv = hw2[(size_t)b * HH + o];
    float tw = vw[o];
    float part[8];
    const float* we = g_W1E + (size_t)b * TT * HH + o;
#pragma unroll
    for (int t = 0; t < TT; t++) part[t] = tw * tanhf(we[t * HH] + hv);
#pragma unroll
    for (int off = 16; off > 0; off >>= 1)
#pragma unroll
        for (int t = 0; t < TT; t++) part[t] += __shfl_down_sync(0xffffffffu, part[t], off);
    if ((o & 31) == 0) {
        int w = o >> 5;
#pragma unroll
        for (int t = 0; t < TT; t++) red[t][w] = part[t];
    }
    __syncthreads();
    if (o < TT) {
        float s = 0.f;
#pragma unroll
        for (int w = 0; w < 16; w++) s += red[o][w];
        s += vb[0];
        ui[o] = s;
        probs[(size_t)b * (TT * TT) + step * TT + o] = s;
    }
    __syncthreads();
    if (o == 0) {
        int m = g_mask[b];
        int best = 0;
        float bv = -3.4e38f;
#pragma unroll
        for (int t = 0; t < TT; t++) {
            bool ok = ((m >> t) & 1) == 0;
            if (ok && ui[t] > bv) { bv = ui[t]; best = t; }
        }
        g_mask[b] = m | (1 << best);
        g_sel[b] = best;
        ptrs[(size_t)b * TT + step] = (float)best;
    }
}

// ---------------- launch ----------------
#define SMEM128 67584    // max(4*128*128 = 65536 mainloop, 128*132*4 = 67584 staging)

extern "C" void kernel_launch(void* const* d_in, const int* in_sizes, int n_in,
                              void* d_out, int out_size) {
    const float* inps   = (const float*)d_in[0];
    const float* enc    = (const float*)d_in[1];
    const float* conv_w = (const float*)d_in[2];
    const float* conv_b = (const float*)d_in[3];
    const float* Wih    = (const float*)d_in[4];
    const float* Whh    = (const float*)d_in[5];
    const float* bih    = (const float*)d_in[6];
    const float* bhh    = (const float*)d_in[7];
    const float* W1     = (const float*)d_in[8];
    const float* b1     = (const float*)d_in[9];
    const float* W2     = (const float*)d_in[10];
    const float* b2     = (const float*)d_in[11];
    const float* vw     = (const float*)d_in[12];
    const float* vb     = (const float*)d_in[13];

    float* probs = (float*)d_out;
    float* ptrs  = probs + (size_t)BN * TT * TT;

    void *pP, *pG, *pW1E, *pbrb, *pzero, *phw2;
    void *pencP, *pinpsP, *pinp0P, *pWrP, *pWhrP, *pW1P, *pW2P, *phPA, *phPB;
    cudaGetSymbolAddress(&pP,     g_P);
    cudaGetSymbolAddress(&pG,     g_G);
    cudaGetSymbolAddress(&pW1E,   g_W1E);
    cudaGetSymbolAddress(&pbrb,   g_brb);
    cudaGetSymbolAddress(&pzero,  g_zero);
    cudaGetSymbolAddress(&phw2,   g_hw2);
    cudaGetSymbolAddress(&pencP,  g_encP);
    cudaGetSymbolAddress(&pinpsP, g_inpsP);
    cudaGetSymbolAddress(&pinp0P, g_inp0P);
    cudaGetSymbolAddress(&pWrP,   g_WrP);
    cudaGetSymbolAddress(&pWhrP,  g_WhrP);
    cudaGetSymbolAddress(&pW1P,   g_W1P);
    cudaGetSymbolAddress(&pW2P,   g_W2P);
    cudaGetSymbolAddress(&phPA,   g_hPA);
    cudaGetSymbolAddress(&phPB,   g_hPB);

    cudaFuncSetAttribute(tgemm_k<0, 128>, cudaFuncAttributeMaxDynamicSharedMemorySize, SMEM128);
    cudaFuncSetAttribute(tgemm_k<2, 128>, cudaFuncAttributeMaxDynamicSharedMemorySize, SMEM128);

    int ei = 0;
    auto rec = [&](cudaStream_t s) -> cudaEvent_t {
        cudaEventRecord(g_ev[ei], s);
        return g_ev[ei++];
    };

    // ---- fork immediately; prologue split across both streams ----
    cudaEvent_t e0 = rec((cudaStream_t)0);
    cudaStreamWaitEvent(g_sA, e0, 0);
    cudaStreamWaitEvent(g_sB, e0, 0);

    // sA: weights reorder+split, inps split, conv (feeds P / P0 / gates)
    prep_k<<<(NG * HH) / 256, 256, 0, g_sA>>>(Wih, Whh, bih, bhh);
    split_k<<<(int)((PS_ENC / 4 + 255) / 256), 256, 0, g_sA>>>((const float4*)inps,
                                                               (__half*)pinpsP, PS_ENC);
    conv_k<<<(BN * HH) / 256, 256, 0, g_sA>>>(enc, conv_w, conv_b);
    init_k<<<BN / 256, 256, 0, g_sA>>>();

    // sB: enc/W1/W2 splits (feeds W1E / hw2), then W1E GEMM
    split_k<<<(int)((PS_ENC / 4 + 255) / 256), 256, 0, g_sB>>>((const float4*)enc,
                                                               (__half*)pencP, PS_ENC);
    split_k<<<(int)((PS_W1 / 4 + 255) / 256), 256, 0, g_sB>>>((const float4*)W1,
                                                              (__half*)pW1P, PS_W1);
    split_k<<<(int)((PS_W1 / 4 + 255) / 256), 256, 0, g_sB>>>((const float4*)W2,
                                                              (__half*)pW2P, PS_W1);
    {
        dim3 g(HH / 128, (BN * TT) / 128);
        tgemm_k<0, 128><<<g, 256, SMEM128, g_sB>>>((const __half*)pencP, PS_ENC,
                                                   (const __half*)pW1P, PS_W1,
                                                   b1, (float*)pW1E, HH, 1, 1, 0, nullptr);
    }

    // ---- sA: P[b*8+t] = inps[b,t] @ Wr^T + brb ----
    {
        dim3 g(NG / 128, (BN * TT) / 128);
        tgemm_k<0, 128><<<g, 256, SMEM128, g_sA>>>((const __half*)pinpsP, PS_ENC,
                                                   (const __half*)pWrP, PS_W,
                                                   (const float*)pbrb, (float*)pP, NG,
                                                   1, 1, 0, nullptr);
    }
    // ---- sA: step-0 gates GEMM (inp0 @ Wr^T) with fused cell epilogue -> h0, c ----
    {
        dim3 g(NG / 128, BN / 128);
        tgemm_k<2, 128><<<g, 256, SMEM128, g_sA>>>((const __half*)pinp0P, PS_INP0,
                                                   (const __half*)pWrP, PS_W,
                                                   (const float*)pbrb, nullptr, 0,
                                                   1, 1, 0, (__half*)phPA);
    }
    cudaEvent_t e_h = rec(g_sA);        // h0 ready

    cudaEvent_t e_attn;
    // ---- step 0 scoring on sB (hw2 now MT=128: same resource shape as gates
    //      so its CTAs pack into shared waves with the concurrent gates GEMM) ----
    cudaStreamWaitEvent(g_sB, e_h, 0);
    {
        dim3 g(HH / 128, BN / 128);
        tgemm_k<0, 128><<<g, 256, SMEM128, g_sB>>>((const __half*)phPA, PS_H,
                                                   (const __half*)pW2P, PS_W1,
                                                   b2, (float*)phw2, HH, 1, 1, 0, nullptr);
    }
    attn_k<<<BN, HH, 0, g_sB>>>((const float*)phw2, vw, vb, probs, ptrs, 0);
    e_attn = rec(g_sB);

    // ---- steps 1..7: gates_{s} (sA, 512 CTAs) and hw2_{s-1} (sB, 128 CTAs)
    //      are dependency-concurrent after cell_{s-1}; identical resource
    //      shapes let them co-schedule into the same waves ----
    for (int s = 1; s < TT; s++) {
        const __half* hin = (s & 1) ? (const __half*)phPA : (const __half*)phPB;
        __half* hout      = (s & 1) ? (__half*)phPB : (__half*)phPA;
        {   // raw G = h_{s-1} @ Whr^T  (no sel dependency)
            dim3 g(NG / 128, BN / 128);
            tgemm_k<0, 128><<<g, 256, SMEM128, g_sA>>>(hin, PS_H,
                                                       (const __half*)pWhrP, PS_W,
                                                       (const float*)pzero, (float*)pG, NG,
                                                       1, 1, 0, nullptr);
        }
        cudaStreamWaitEvent(g_sA, e_attn, 0);     // sel_{s-1} needed only by cell
        cell_k<<<(BN * HH) / 256, 256, 0, g_sA>>>((const float*)pG, hout);
        cudaEvent_t e_cell = rec(g_sA);

        cudaStreamWaitEvent(g_sB, e_cell, 0);
        {
            dim3 g(HH / 128, BN / 128);
            tgemm_k<0, 128><<<g, 256, SMEM128, g_sB>>>((const __half*)hout, PS_H,
                                                       (const __half*)pW2P, PS_W1,
                                                       b2, (float*)phw2, HH, 1, 1, 0, nullptr);
        }
        attn_k<<<BN, HH, 0, g_sB>>>((const float*)phw2, vw, vb, probs, ptrs, s);
        e_attn = rec(g_sB);
    }

    // ---- join both streams back into the capture-origin stream ----
    cudaEvent_t eA = rec(g_sA);
    cudaStreamWaitEvent((cudaStream_t)0, eA, 0);
    cudaStreamWaitEvent((cudaStream_t)0, e_attn, 0);
}

// round 15
// speedup vs baseline: 1.0484x; 1.0082x over previous
#include <cuda_runtime.h>
#include <cuda_fp16.h>
#include <math.h>
#include <stdint.h>

// Problem constants
#define BN   4096
#define TT   8
#define HH   512
#define NG   2048
#define KK   512                  // inner dim of every GEMM

// plane strides (elements)
#define PS_ENC  ((size_t)32768 * 512)
#define PS_INP0 ((size_t)4096 * 512)
#define PS_W    ((size_t)2048 * 512)
#define PS_W1   ((size_t)512 * 512)
#define PS_H    ((size_t)4096 * 512)

// ---------------- device scratch ----------------
__device__ float g_P[(size_t)BN * 8 * NG];      // input-side gates, row b*8+t
__device__ float g_G[(size_t)BN * NG];          // raw h@Whr^T for current step
__device__ float g_W1E[(size_t)BN * TT * HH];
__device__ float g_brb[NG];
__device__ float g_zero[NG];                    // stays zero (module-load init)
__device__ float g_c  [(size_t)BN * HH];
__device__ float g_hw2[(size_t)BN * HH];
__device__ int   g_sel [BN];
__device__ int   g_mask[BN];

// fp16x2 plane arrays: [plane][rows][512], plane 0 = hi, 1 = lo
__device__ __half g_encP [2 * PS_ENC];
__device__ __half g_inpsP[2 * PS_ENC];
__device__ __half g_inp0P[2 * PS_INP0];
__device__ __half g_WrP  [2 * PS_W];
__device__ __half g_WhrP [2 * PS_W];
__device__ __half g_W1P  [2 * PS_W1];
__device__ __half g_W2P  [2 * PS_W1];
__device__ __half g_hPA  [2 * PS_H];
__device__ __half g_hPB  [2 * PS_H];

// ---------------- streams/events: created once at image load, reused every call
static cudaStream_t g_sA, g_sB;
static cudaEvent_t  g_ev[64];
namespace {
struct StreamInit {
    StreamInit() {
        cudaStreamCreateWithFlags(&g_sA, cudaStreamNonBlocking);
        cudaStreamCreateWithFlags(&g_sB, cudaStreamNonBlocking);
        for (int i = 0; i < 64; i++)
            cudaEventCreateWithFlags(&g_ev[i], cudaEventDisableTiming);
    }
};
StreamInit g_si;
}

__device__ __forceinline__ float sigm(float x) { return 1.0f / (1.0f + expf(-x)); }

__device__ __forceinline__ uint32_t smem_to_u32(const void* p) {
    uint32_t a;
    asm("{ .reg .u64 t; cvta.to.shared.u64 t, %1; cvt.u32.u64 %0, t; }" : "=r"(a) : "l"(p));
    return a;
}
__device__ __forceinline__ void cp16(uint32_t dst, const void* src) {
    asm volatile("cp.async.cg.shared.global [%0], [%1], 16;" :: "r"(dst), "l"(src));
}
__device__ __forceinline__ void ldsm4(uint32_t* r, uint32_t addr) {
    asm volatile("ldmatrix.sync.aligned.m8n8.x4.shared.b16 {%0,%1,%2,%3}, [%4];"
                 : "=r"(r[0]), "=r"(r[1]), "=r"(r[2]), "=r"(r[3]) : "r"(addr));
}
__device__ __forceinline__ void mma16816(float* c, const uint32_t* a, uint32_t b0, uint32_t b1) {
    asm volatile("mma.sync.aligned.m16n8k16.row.col.f32.f16.f16.f32 "
                 "{%0,%1,%2,%3},{%4,%5,%6,%7},{%8,%9},{%0,%1,%2,%3};"
                 : "+f"(c[0]), "+f"(c[1]), "+f"(c[2]), "+f"(c[3])
                 : "r"(a[0]), "r"(a[1]), "r"(a[2]), "r"(a[3]), "r"(b0), "r"(b1));
}

// 2-way fp16 split: x = hi + lo, |lo| <= 2^-11 |x|, dropped lo*lo ~ 2^-22
__device__ __forceinline__ void s2(float x, __half& a, __half& b) {
    a = __float2half_rn(x);
    b = __float2half_rn(x - __half2float(a));
}
__device__ __forceinline__ uint32_t pk2(__half a, __half b) {
    __half2 t = __halves2half2(a, b);
    return *(uint32_t*)&t;
}

// ---------------- small kernels ----------------
__global__ void split_k(const float4* __restrict__ src, __half* __restrict__ dst, size_t n) {
    size_t i = (size_t)blockIdx.x * blockDim.x + threadIdx.x;
    if (i >= (n >> 2)) return;
    float4 v = src[i];
    __half h[4], l[4];
    s2(v.x, h[0], l[0]); s2(v.y, h[1], l[1]);
    s2(v.z, h[2], l[2]); s2(v.w, h[3], l[3]);
    uint2 t;
    t.x = pk2(h[0], h[1]); t.y = pk2(h[2], h[3]);
    *(uint2*)(dst + 4 * i) = t;
    t.x = pk2(l[0], l[1]); t.y = pk2(l[2], l[3]);
    *(uint2*)(dst + n + 4 * i) = t;
}

// reorder LSTM weights to gate-quad order (n = 4*j+g) and split to planes
__global__ void prep_k(const float* __restrict__ Wih, const float* __restrict__ Whh,
                       const float* __restrict__ bih, const float* __restrict__ bhh) {
    int idx = blockIdx.x * blockDim.x + threadIdx.x;   // NG*HH
    int n = idx >> 9, k = idx & 511;
    int j = n >> 2, g = n & 3;
    int src = (g * 512 + j) * 512 + k;
    __half h, l;
    s2(Wih[src], h, l);
    g_WrP[idx] = h; g_WrP[idx + PS_W] = l;
    s2(Whh[src], h, l);
    g_WhrP[idx] = h; g_WhrP[idx + PS_W] = l;
    if (k == 0) g_brb[n] = bih[g * 512 + j] + bhh[g * 512 + j];
}

__global__ void conv_k(const float* __restrict__ enc, const float* __restrict__ cw,
                       const float* __restrict__ cb) {
    int idx = blockIdx.x * blockDim.x + threadIdx.x;   // BN*HH
    int b = idx >> 9, hh = idx & 511;
    const float* e = enc + (size_t)b * TT * HH + hh;
    float s = cb[0];
#pragma unroll
    for (int t = 0; t < TT; t++) s += e[t * HH] * cw[t];
    __half h, l;
    s2(s, h, l);
    g_inp0P[idx] = h; g_inp0P[idx + PS_INP0] = l;
}

__global__ void init_k() {   // mask MUST reset every launch for graph replay
    int idx = blockIdx.x * blockDim.x + threadIdx.x;
    if (idx < BN) g_mask[idx] = 0;
}

// per-step LSTM cell (s>=1): gates = G + P[b*8+sel]; update c; write h planes
__global__ void cell_k(const float* __restrict__ G, __half* __restrict__ houtP) {
    int idx = blockIdx.x * blockDim.x + threadIdx.x;   // BN*HH
    int b = idx >> 9, hidx = idx & 511;
    int sel = g_sel[b];
    float4 gv = *(const float4*)(G + (size_t)b * NG + hidx * 4);
    float4 pv = *(const float4*)(g_P + ((size_t)b * 8 + sel) * NG + hidx * 4);
    float gi = gv.x + pv.x, gf = gv.y + pv.y, gg = gv.z + pv.z, go = gv.w + pv.w;
    float co = g_c[idx];
    float cn = sigm(gf) * co + sigm(gi) * tanhf(gg);
    float hv = sigm(go) * tanhf(cn);
    g_c[idx] = cn;
    __half hh, hl;
    s2(hv, hh, hl);
    houtP[idx] = hh;
    houtP[idx + PS_H] = hl;
}

// ---------------- fp16x2 (3-pass) emulated fp32 GEMM via mma.sync ----------------
// C[m,n] = sum_k A[m,k]*W[n,k], K=512. CTA MTx128, k-chunk 64.
// smem: 2 A planes + 2 B planes (hi, lo). Passes: hi*lo, lo*hi, hi*hi.
// EPI==0: Out[dstrow(m)*ldo+n] = C + bias[n], dstrow=(m/grp)*rowmul+m%grp+rowoff
// EPI==2 (MT=128): step-0 LSTM cell: gates = C + bias(brb); c0=0; write g_c + h planes
template <int EPI, int MT>
__global__ void __launch_bounds__(256, (MT == 128 ? 2 : 3))
tgemm_k(const __half* __restrict__ Ap, size_t APS,
        const __half* __restrict__ Wp, size_t WPS,
        const float* __restrict__ bias,
        float* __restrict__ Out, int ldo,
        int grp, int rowmul, int rowoff,
        __half* __restrict__ houtP) {
    constexpr int MF     = MT / 64;
    constexpr int APL    = MT * 128;         // bytes per A plane tile (64 fp16/row)
    constexpr int ABYTES = 2 * APL;
    constexpr int AQ     = 2 * MT * 8;       // A 16B-quads per chunk
    constexpr int ITER   = (AQ + 2048) / 256;

    extern __shared__ char smc[];
    uint32_t smb = smem_to_u32(smc);
    int tid = threadIdx.x, lane = tid & 31, wid = tid >> 5;
    int wm = wid >> 1, wn = wid & 1;
    int m0 = blockIdx.y * MT, n0 = blockIdx.x * 128;

    int la_r = lane & 15, la_c = (lane >> 4) * 16;
    uint32_t rowA = (uint32_t)(la_r * 128);
    uint32_t swA  = (uint32_t)((la_r & 7) << 4);
    int lb_r = (lane & 7) + ((lane >> 4) & 1) * 8;
    int lb_c = ((lane >> 3) & 1) * 16;
    uint32_t rowB = (uint32_t)(lb_r * 128);
    uint32_t swB  = (uint32_t)((lb_r & 7) << 4);

    float c[MF][8][4];
#pragma unroll
    for (int i = 0; i < MF; i++)
#pragma unroll
        for (int j = 0; j < 8; j++)
#pragma unroll
            for (int q = 0; q < 4; q++) c[i][j][q] = 0.0f;

    for (int kc = 0; kc < 8; kc++) {
        int kb = kc * 64;
#pragma unroll
        for (int it = 0; it < ITER; it++) {
            int q = tid + it * 256;
            const __half* src;
            uint32_t dst;
            if (q < AQ) {
                int tile = q / (MT * 8), rem = q % (MT * 8), row = rem >> 3, c16 = rem & 7;
                src = Ap + (size_t)tile * APS + (size_t)(m0 + row) * KK + kb + c16 * 8;
                dst = smb + tile * APL + row * 128 + ((c16 * 16) ^ ((row & 7) << 4));
            } else {
                int qb = q - AQ;
                int tile = qb >> 10, rem = qb & 1023, row = rem >> 3, c16 = rem & 7;
                src = Wp + (size_t)tile * WPS + (size_t)(n0 + row) * KK + kb + c16 * 8;
                dst = smb + ABYTES + tile * 16384 + row * 128 + ((c16 * 16) ^ ((row & 7) << 4));
            }
            cp16(dst, src);
        }
        asm volatile("cp.async.commit_group;");
        asm volatile("cp.async.wait_group 0;" ::: "memory");
        __syncthreads();

#pragma unroll
        for (int s = 0; s < 4; s++) {
            uint32_t a[2][MF][4];
#pragma unroll
            for (int pl = 0; pl < 2; pl++)
#pragma unroll
                for (int mf = 0; mf < MF; mf++)
                    ldsm4(a[pl][mf],
                          smb + pl * APL + (wm * 16 * MF + mf * 16) * 128 + rowA
                              + (((uint32_t)(la_c + s * 32)) ^ swA));
            // pass order per accumulator (small -> large): hi*lo, lo*hi, hi*hi
#pragma unroll
            for (int pbi = 0; pbi < 2; pbi++) {
                int pb = 1 - pbi;                 // B plane: lo first, then hi
                uint32_t b[4][4];
#pragma unroll
                for (int n2 = 0; n2 < 4; n2++)
                    ldsm4(b[n2], smb + ABYTES + pb * 16384
                                 + (wn * 64 + n2 * 16) * 128 + rowB
                                 + (((uint32_t)(lb_c + s * 32)) ^ swB));
                int npa = (pb == 1) ? 1 : 2;      // pb=1: pa=0; pb=0: pa=1 then 0
#pragma unroll
                for (int pi = 0; pi < 2; pi++) {
                    if (pi >= npa) continue;
                    int pa = (pb == 1) ? 0 : (1 - pi);
#pragma unroll
                    for (int n2 = 0; n2 < 4; n2++) {
#pragma unroll
                        for (int mf = 0; mf < MF; mf++) {
                            mma16816(c[mf][n2 * 2],     a[pa][mf], b[n2][0], b[n2][1]);
                            mma16816(c[mf][n2 * 2 + 1], a[pa][mf], b[n2][2], b[n2][3]);
                        }
                    }
                }
            }
        }
        __syncthreads();
    }

    // stage C to smem: stg[MT][132] fp32
    float* stg = (float*)smc;
#pragma unroll
    for (int mf = 0; mf < MF; mf++)
#pragma unroll
        for (int nf = 0; nf < 8; nf++) {
            int r = wm * 16 * MF + mf * 16 + (lane >> 2);
            int cc = wn * 64 + nf * 8 + (lane & 3) * 2;
            *(float2*)&stg[r * 132 + cc] = make_float2(c[mf][nf][0], c[mf][nf][1]);
            *(float2*)&stg[(r + 8) * 132 + cc] = make_float2(c[mf][nf][2], c[mf][nf][3]);
        }
    __syncthreads();

    if (EPI == 0) {
        constexpr int GPR = 256 / MT;
        constexpr int CPG = 128 / GPR;
        int r = tid / GPR, cb = (tid % GPR) * CPG;
        int gr = m0 + r;
        int dr = (gr / grp) * rowmul + (gr % grp) + rowoff;
        float* op = Out + (size_t)dr * ldo + n0 + cb;
        const float* bp = bias + n0 + cb;
        const float* sr = stg + r * 132 + cb;
#pragma unroll
        for (int j = 0; j < CPG; j += 4) {
            float4 v;
            v.x = sr[j] + bp[j];         v.y = sr[j + 1] + bp[j + 1];
            v.z = sr[j + 2] + bp[j + 2]; v.w = sr[j + 3] + bp[j + 3];
            *(float4*)(op + j) = v;
        }
    } else if (MT == 128) {
        // EPI==2: step-0 LSTM cell, c0 = 0
        int hl = tid & 15, rg = tid >> 4;
#pragma unroll
        for (int i = 0; i < 8; i++) {
            int row = rg * 8 + i, b = m0 + row;
#pragma unroll
            for (int half = 0; half < 2; half++) {
                const float* sr = stg + row * 132 + half * 64 + hl * 4;
                const float* bp = bias + n0 + half * 64 + hl * 4;
                float gi = sr[0] + bp[0];
                float gg = sr[2] + bp[2];
                float go = sr[3] + bp[3];
                int hidx = (n0 >> 2) + half * 16 + hl;
                size_t off = (size_t)b * HH + hidx;
                float cn = sigm(gi) * tanhf(gg);       // sigm(f)*c0 = 0
                float hv = sigm(go) * tanhf(cn);
                g_c[off] = cn;
                __half hh, hlv;
                s2(hv, hh, hlv);
                houtP[off] = hh;
                houtP[off + PS_H] = hlv;
            }
        }
    }
}

// ---------------- fused attention step ----------------
__global__ void attn_k(const float* __restrict__ hw2,
                       const float* __restrict__ vw, const float* __restrict__ vb,
                       float* __restrict__ probs, float* __restrict__ ptrs, int step) {
    __shared__ float red[8][16];
    __shared__ float ui[8];
    int b = blockIdx.x, o = threadIdx.x;

    float hv = hw2[(size_t)b * HH + o];
    float tw = vw[o];
    float part[8];
    const float* we = g_W1E + (size_t)b * TT * HH + o;
#pragma unroll
    for (int t = 0; t < TT; t++) part[t] = tw * tanhf(we[t * HH] + hv);
#pragma unroll
    for (int off = 16; off > 0; off >>= 1)
#pragma unroll
        for (int t = 0; t < TT; t++) part[t] += __shfl_down_sync(0xffffffffu, part[t], off);
    if ((o & 31) == 0) {
        int w = o >> 5;
#pragma unroll
        for (int t = 0; t < TT; t++) red[t][w] = part[t];
    }
    __syncthreads();
    if (o < TT) {
        float s = 0.f;
#pragma unroll
        for (int w = 0; w < 16; w++) s += red[o][w];
        s += vb[0];
        ui[o] = s;
        probs[(size_t)b * (TT * TT) + step * TT + o] = s;
    }
    __syncthreads();
    if (o == 0) {
        int m = g_mask[b];
        int best = 0;
        float bv = -3.4e38f;
#pragma unroll
        for (int t = 0; t < TT; t++) {
            bool ok = ((m >> t) & 1) == 0;
            if (ok && ui[t] > bv) { bv = ui[t]; best = t; }
        }
        g_mask[b] = m | (1 << best);
        g_sel[b] = best;
        ptrs[(size_t)b * TT + step] = (float)best;
    }
}

// ---------------- launch ----------------
#define SMEM128 67584    // max(4*128*128 = 65536 mainloop, 128*132*4 = 67584 staging)

extern "C" void kernel_launch(void* const* d_in, const int* in_sizes, int n_in,
                              void* d_out, int out_size) {
    const float* inps   = (const float*)d_in[0];
    const float* enc    = (const float*)d_in[1];
    const float* conv_w = (const float*)d_in[2];
    const float* conv_b = (const float*)d_in[3];
    const float* Wih    = (const float*)d_in[4];
    const float* Whh    = (const float*)d_in[5];
    const float* bih    = (const float*)d_in[6];
    const float* bhh    = (const float*)d_in[7];
    const float* W1     = (const float*)d_in[8];
    const float* b1     = (const float*)d_in[9];
    const float* W2     = (const float*)d_in[10];
    const float* b2     = (const float*)d_in[11];
    const float* vw     = (const float*)d_in[12];
    const float* vb     = (const float*)d_in[13];

    float* probs = (float*)d_out;
    float* ptrs  = probs + (size_t)BN * TT * TT;

    void *pP, *pG, *pW1E, *pbrb, *pzero, *phw2;
    void *pencP, *pinpsP, *pinp0P, *pWrP, *pWhrP, *pW1P, *pW2P, *phPA, *phPB;
    cudaGetSymbolAddress(&pP,     g_P);
    cudaGetSymbolAddress(&pG,     g_G);
    cudaGetSymbolAddress(&pW1E,   g_W1E);
    cudaGetSymbolAddress(&pbrb,   g_brb);
    cudaGetSymbolAddress(&pzero,  g_zero);
    cudaGetSymbolAddress(&phw2,   g_hw2);
    cudaGetSymbolAddress(&pencP,  g_encP);
    cudaGetSymbolAddress(&pinpsP, g_inpsP);
    cudaGetSymbolAddress(&pinp0P, g_inp0P);
    cudaGetSymbolAddress(&pWrP,   g_WrP);
    cudaGetSymbolAddress(&pWhrP,  g_WhrP);
    cudaGetSymbolAddress(&pW1P,   g_W1P);
    cudaGetSymbolAddress(&pW2P,   g_W2P);
    cudaGetSymbolAddress(&phPA,   g_hPA);
    cudaGetSymbolAddress(&phPB,   g_hPB);

    cudaFuncSetAttribute(tgemm_k<0, 128>, cudaFuncAttributeMaxDynamicSharedMemorySize, SMEM128);
    cudaFuncSetAttribute(tgemm_k<2, 128>, cudaFuncAttributeMaxDynamicSharedMemorySize, SMEM128);

    int ei = 0;
    auto rec = [&](cudaStream_t s) -> cudaEvent_t {
        cudaEventRecord(g_ev[ei], s);
        return g_ev[ei++];
    };

    // ---- fork immediately ----
    cudaEvent_t e0 = rec((cudaStream_t)0);
    cudaStreamWaitEvent(g_sA, e0, 0);
    cudaStreamWaitEvent(g_sB, e0, 0);

    // ---- sA: prep -> conv -> init -> P0 (h0) -> split(inps) -> P (big GEMM)
    //      P is needed only by cell_1, so it runs CONCURRENT with step 0 +
    //      gates_1 on sB, filling their idle SM slots. ----
    prep_k<<<(NG * HH) / 256, 256, 0, g_sA>>>(Wih, Whh, bih, bhh);
    conv_k<<<(BN * HH) / 256, 256, 0, g_sA>>>(enc, conv_w, conv_b);
    init_k<<<BN / 256, 256, 0, g_sA>>>();
    {   // P0: step-0 gates GEMM (inp0 @ Wr^T) with fused cell -> h0, c
        dim3 g(NG / 128, BN / 128);
        tgemm_k<2, 128><<<g, 256, SMEM128, g_sA>>>((const __half*)pinp0P, PS_INP0,
                                                   (const __half*)pWrP, PS_W,
                                                   (const float*)pbrb, nullptr, 0,
                                                   1, 1, 0, (__half*)phPA);
    }
    cudaEvent_t e_h0 = rec(g_sA);
    split_k<<<(int)((PS_ENC / 4 + 255) / 256), 256, 0, g_sA>>>((const float4*)inps,
                                                               (__half*)pinpsP, PS_ENC);
    {   // P[b*8+t] = inps[b,t] @ Wr^T + brb
        dim3 g(NG / 128, (BN * TT) / 128);
        tgemm_k<0, 128><<<g, 256, SMEM128, g_sA>>>((const __half*)pinpsP, PS_ENC,
                                                   (const __half*)pWrP, PS_W,
                                                   (const float*)pbrb, (float*)pP, NG,
                                                   1, 1, 0, nullptr);
    }
    cudaEvent_t e_P = rec(g_sA);

    // ---- sB: splits + W1E, then step 0 + gates_1 (all independent of P) ----
    split_k<<<(int)((PS_ENC / 4 + 255) / 256), 256, 0, g_sB>>>((const float4*)enc,
                                                               (__half*)pencP, PS_ENC);
    split_k<<<(int)((PS_W1 / 4 + 255) / 256), 256, 0, g_sB>>>((const float4*)W1,
                                                              (__half*)pW1P, PS_W1);
    split_k<<<(int)((PS_W1 / 4 + 255) / 256), 256, 0, g_sB>>>((const float4*)W2,
                                                              (__half*)pW2P, PS_W1);
    {   // W1E = enc @ W1^T + b1
        dim3 g(HH / 128, (BN * TT) / 128);
        tgemm_k<0, 128><<<g, 256, SMEM128, g_sB>>>((const __half*)pencP, PS_ENC,
                                                   (const __half*)pW1P, PS_W1,
                                                   b1, (float*)pW1E, HH, 1, 1, 0, nullptr);
    }
    cudaStreamWaitEvent(g_sB, e_h0, 0);
    {   // hw2_0
        dim3 g(HH / 128, BN / 128);
        tgemm_k<0, 128><<<g, 256, SMEM128, g_sB>>>((const __half*)phPA, PS_H,
                                                   (const __half*)pW2P, PS_W1,
                                                   b2, (float*)phw2, HH, 1, 1, 0, nullptr);
    }
    attn_k<<<BN, HH, 0, g_sB>>>((const float*)phw2, vw, vb, probs, ptrs, 0);
    {   // gates_1: G = h0 @ Whr^T  (doesn't need P or sel)
        dim3 g(NG / 128, BN / 128);
        tgemm_k<0, 128><<<g, 256, SMEM128, g_sB>>>((const __half*)phPA, PS_H,
                                                   (const __half*)pWhrP, PS_W,
                                                   (const float*)pzero, (float*)pG, NG,
                                                   1, 1, 0, nullptr);
    }
    cudaStreamWaitEvent(g_sB, e_P, 0);     // cell_1 needs P
    cell_k<<<(BN * HH) / 256, 256, 0, g_sB>>>((const float*)pG, (__half*)phPB);
    cudaEvent_t e_cell1 = rec(g_sB);
    {   // hw2_1
        dim3 g(HH / 128, BN / 128);
        tgemm_k<0, 128><<<g, 256, SMEM128, g_sB>>>((const __half*)phPB, PS_H,
                                                   (const __half*)pW2P, PS_W1,
                                                   b2, (float*)phw2, HH, 1, 1, 0, nullptr);
    }
    attn_k<<<BN, HH, 0, g_sB>>>((const float*)phw2, vw, vb, probs, ptrs, 1);
    cudaEvent_t e_attn = rec(g_sB);

    // ---- steps 2..7: round-14 two-stream pattern ----
    cudaStreamWaitEvent(g_sA, e_cell1, 0);
    for (int s = 2; s < TT; s++) {
        const __half* hin = (s & 1) ? (const __half*)phPA : (const __half*)phPB;
        __half* hout      = (s & 1) ? (__half*)phPB : (__half*)phPA;
        {   // raw G = h_{s-1} @ Whr^T
            dim3 g(NG / 128, BN / 128);
            tgemm_k<0, 128><<<g, 256, SMEM128, g_sA>>>(hin, PS_H,
                                                       (const __half*)pWhrP, PS_W,
                                                       (const float*)pzero, (float*)pG, NG,
                                                       1, 1, 0, nullptr);
        }
        cudaStreamWaitEvent(g_sA, e_attn, 0);     // sel_{s-1} needed only by cell
        cell_k<<<(BN * HH) / 256, 256, 0, g_sA>>>((const float*)pG, hout);
        cudaEvent_t e_cell = rec(g_sA);

        cudaStreamWaitEvent(g_sB, e_cell, 0);
        {
            dim3 g(HH / 128, BN / 128);
            tgemm_k<0, 128><<<g, 256, SMEM128, g_sB>>>((const __half*)hout, PS_H,
                                                       (const __half*)pW2P, PS_W1,
                                                       b2, (float*)phw2, HH, 1, 1, 0, nullptr);
        }
        attn_k<<<BN, HH, 0, g_sB>>>((const float*)phw2, vw, vb, probs, ptrs, s);
        e_attn = rec(g_sB);
    }

    // ---- join both streams back into the capture-origin stream ----
    cudaEvent_t eA = rec(g_sA);
    cudaStreamWaitEvent((cudaStream_t)0, eA, 0);
    cudaStreamWaitEvent((cudaStream_t)0, e_attn, 0);
}